// round 6
// baseline (speedup 1.0000x reference)
#include <cuda_runtime.h>

typedef unsigned long long ull;

// ---- packed f32x2 helpers (sm_100+) ---------------------------------------
__device__ __forceinline__ ull f2pack(float lo, float hi) {
    ull r; asm("mov.b64 %0, {%1, %2};" : "=l"(r) : "f"(lo), "f"(hi)); return r;
}
__device__ __forceinline__ void f2unpack(ull v, float& lo, float& hi) {
    asm("mov.b64 {%0, %1}, %2;" : "=f"(lo), "=f"(hi) : "l"(v));
}
__device__ __forceinline__ ull ffma2(ull a, ull b, ull c) {
    ull d; asm("fma.rn.f32x2 %0, %1, %2, %3;" : "=l"(d) : "l"(a), "l"(b), "l"(c));
    return d;
}

// Scratch (device globals — no allocation allowed)
__device__ float g_qkv[1024 * 1536];   // [B*N][3C]
__device__ float g_att[1024 * 512];    // [B*N][C]

// ---------------------------------------------------------------------------
// GEMM: C[M][N] = A[M][K] @ B[N][K]^T (+ bias[N]), packed FFMA2.
// Tile: BM=64 x BN=8*CPT, BK=16, 256 threads, 2 rows x CPT cols per thread.
// A broadcast-read (float2, 4 distinct addrs/warp); B read as raw ull pairs
// (no packing); only 2 MOV-dups per k per thread. Register prefetch of the
// next gmem tile hides LDG latency.
// ---------------------------------------------------------------------------
template<int CPT, bool HAS_BIAS>   // CPT = cols per thread (4 or 8)
__global__ __launch_bounds__(256) void gemm_f2(
    const float* __restrict__ A, const float* __restrict__ B,
    const float* __restrict__ bias, float* __restrict__ C,
    int M, int N, int K)
{
    const int BN = 8 * CPT;
    __shared__ __align__(16) float As[16][66];       // stride 66: 8B-aligned rows
    __shared__ __align__(16) float Bs[16][BN + 4];   // 16B-aligned rows

    int tid = threadIdx.x;
    int tx = tid & 7;        // 8 col groups of CPT
    int ty = tid >> 3;       // 32 row groups of 2
    int row0 = blockIdx.y * 64;
    int col0 = blockIdx.x * BN;

    ull acc[2][CPT / 2];
    #pragma unroll
    for (int i = 0; i < 2; i++)
        #pragma unroll
        for (int j = 0; j < CPT / 2; j++) acc[i][j] = 0ull;

    int lr = tid >> 2;           // 0..63
    int lk = (tid & 3) * 4;      // 0,4,8,12
    const float* Ap = A + (size_t)(row0 + lr) * K + lk;
    const bool bload = (lr < BN);
    const float* Bp = B + (size_t)(col0 + lr) * K + lk;

    float4 aN = *(const float4*)Ap;
    float4 bN = make_float4(0.f, 0.f, 0.f, 0.f);
    if (bload) bN = *(const float4*)Bp;

    for (int k0 = 0; k0 < K; k0 += 16) {
        As[lk + 0][lr] = aN.x; As[lk + 1][lr] = aN.y;
        As[lk + 2][lr] = aN.z; As[lk + 3][lr] = aN.w;
        if (bload) {
            Bs[lk + 0][lr] = bN.x; Bs[lk + 1][lr] = bN.y;
            Bs[lk + 2][lr] = bN.z; Bs[lk + 3][lr] = bN.w;
        }
        __syncthreads();

        if (k0 + 16 < K) {
            aN = *(const float4*)(Ap + k0 + 16);
            if (bload) bN = *(const float4*)(Bp + k0 + 16);
        }

        #pragma unroll
        for (int k = 0; k < 16; k++) {
            float2 a2 = *(const float2*)&As[k][2 * ty];
            ull a0 = f2pack(a2.x, a2.x);
            ull a1 = f2pack(a2.y, a2.y);
            ull bb[CPT / 2];
            {
                ulonglong2 u0 = *(const ulonglong2*)&Bs[k][CPT * tx];
                bb[0] = u0.x; bb[1] = u0.y;
                if (CPT == 8) {
                    ulonglong2 u1 = *(const ulonglong2*)&Bs[k][CPT * tx + 4];
                    bb[2] = u1.x; bb[3] = u1.y;
                }
            }
            #pragma unroll
            for (int j = 0; j < CPT / 2; j++) {
                acc[0][j] = ffma2(a0, bb[j], acc[0][j]);
                acc[1][j] = ffma2(a1, bb[j], acc[1][j]);
            }
        }
        __syncthreads();
    }

    float bv[CPT];
    #pragma unroll
    for (int j = 0; j < CPT; j++)
        bv[j] = HAS_BIAS ? bias[col0 + CPT * tx + j] : 0.f;

    #pragma unroll
    for (int i = 0; i < 2; i++) {
        float o[CPT];
        #pragma unroll
        for (int j = 0; j < CPT / 2; j++) f2unpack(acc[i][j], o[2 * j], o[2 * j + 1]);
        #pragma unroll
        for (int j = 0; j < CPT; j++) o[j] += bv[j];
        float* cp = &C[(size_t)(row0 + 2 * ty + i) * N + col0 + CPT * tx];
        *(float4*)cp = make_float4(o[0], o[1], o[2], o[3]);
        if (CPT == 8)
            *(float4*)(cp + 4) = make_float4(o[4], o[5], o[6], o[7]);
    }
}

// ---------------------------------------------------------------------------
// Fourier attention core (unchanged from R3 — passed, rel_err 3.1e-4).
// Grid: (4 q-tiles of 64, B*H=32). Block: 256 threads.
// score = R^64 * prod_{4 chunks of 16 dims} [prod sin(u) / prod u], u=R(q-k).
// ---------------------------------------------------------------------------
__global__ __launch_bounds__(256) void attn_kernel(
    const float* __restrict__ qkv, const float* __restrict__ paramR,
    float* __restrict__ outp)
{
    extern __shared__ float sm[];
    float* kS = sm;               // [256][64] : -R * k
    float* vS = sm + 256 * 64;    // [256][64] : v

    int tid = threadIdx.x;
    int bh = blockIdx.y;
    int b = bh >> 3;
    int h = bh & 7;
    int qbase = blockIdx.x * 64;
    float R = paramR[0];

    const float* base = qkv + (size_t)(b * 256) * 1536 + h * 64;

    for (int i = tid; i < 256 * 16; i += 256) {
        int n = i >> 4;
        int d4 = (i & 15) << 2;
        float4 kv = *(const float4*)(base + (size_t)n * 1536 + 512 + d4);
        float4 ks;
        ks.x = -R * kv.x; ks.y = -R * kv.y; ks.z = -R * kv.z; ks.w = -R * kv.w;
        *(float4*)&kS[n * 64 + d4] = ks;
        *(float4*)&vS[n * 64 + d4] = *(const float4*)(base + (size_t)n * 1536 + 1024 + d4);
    }

    int q = tid & 63;
    int sub = tid >> 6;

    const float* qp = base + (size_t)(qbase + q) * 1536;
    float qr[64];
    #pragma unroll
    for (int d = 0; d < 64; d += 4) {
        float4 t = *(const float4*)(qp + d);
        qr[d + 0] = R * t.x; qr[d + 1] = R * t.y;
        qr[d + 2] = R * t.z; qr[d + 3] = R * t.w;
    }
    float R64;
    { float p = R; p *= p; p *= p; p *= p; p *= p; p *= p; p *= p; R64 = p; }

    __syncthreads();

    ull acc2[32];
    #pragma unroll
    for (int j = 0; j < 32; j++) acc2[j] = 0ull;
    float sumA = 0.f;

    const int kstart = sub * 64;
    for (int kk = kstart; kk < kstart + 64; kk++) {
        const float* kp = &kS[kk * 64];
        const float4* kp4 = (const float4*)kp;
        float sc = R64;
        #pragma unroll
        for (int c = 0; c < 4; c++) {
            float pn = 1.f, pd = 1.f;
            #pragma unroll
            for (int j4 = 0; j4 < 4; j4++) {
                float4 kv = kp4[c * 4 + j4];
                int dd = c * 16 + j4 * 4;
                float u0 = qr[dd + 0] + kv.x;
                float u1 = qr[dd + 1] + kv.y;
                float u2 = qr[dd + 2] + kv.z;
                float u3 = qr[dd + 3] + kv.w;
                float s0 = __sinf(u0), s1 = __sinf(u1);
                float s2 = __sinf(u2), s3 = __sinf(u3);
                pn *= (s0 * s1) * (s2 * s3);
                pd *= (u0 * u1) * (u2 * u3);
            }
            float r;
            if (pd != 0.f) {
                r = __fdividef(pn, pd);
            } else {
                // exact-zero diff on some dim (reference: factor -> R, ratio 1)
                r = 1.f;
                #pragma unroll 1
                for (int j = c * 16; j < c * 16 + 16; j++) {
                    float u = R * qp[j] + kp[j];
                    if (u != 0.f) r *= __fdividef(__sinf(u), u);
                }
            }
            sc *= r;
        }
        float a2 = sc * sc;
        float a4 = a2 * a2;
        sumA += a4;
        ull a42 = f2pack(a4, a4);
        const ulonglong2* vp = (const ulonglong2*)&vS[kk * 64];
        #pragma unroll
        for (int j = 0; j < 16; j++) {
            ulonglong2 vv = vp[j];
            acc2[2 * j]     = ffma2(a42, vv.x, acc2[2 * j]);
            acc2[2 * j + 1] = ffma2(a42, vv.y, acc2[2 * j + 1]);
        }
    }

    __syncthreads();   // done reading kS/vS — reuse smem for reduction

    float* red = sm;   // [256][65]
    {
        float* rp = red + (sub * 64 + q) * 65;
        #pragma unroll
        for (int j = 0; j < 32; j++) {
            float lo, hi;
            f2unpack(acc2[j], lo, hi);
            rp[2 * j] = lo; rp[2 * j + 1] = hi;
        }
        rp[64] = sumA;
    }
    __syncthreads();

    {
        int q2 = tid & 63;
        int part = tid >> 6;
        const float* r0 = red + q2 * 65;
        const float* r1 = red + (64 + q2) * 65;
        const float* r2 = red + (128 + q2) * 65;
        const float* r3 = red + (192 + q2) * 65;
        float stot = r0[64] + r1[64] + r2[64] + r3[64];
        float inv = __fdividef(1.0f, stot + 1e-6f);
        float* dst = outp + (size_t)(b * 256 + qbase + q2) * 512 + h * 64;
        #pragma unroll
        for (int d = part * 16; d < part * 16 + 16; d++) {
            dst[d] = (r0[d] + r1[d] + r2[d] + r3[d]) * inv;
        }
    }
}

// ---------------------------------------------------------------------------
extern "C" void kernel_launch(void* const* d_in, const int* in_sizes, int n_in,
                              void* d_out, int out_size)
{
    const float* x      = (const float*)d_in[0];   // (4,256,512)
    const float* w_qkv  = (const float*)d_in[1];   // (1536,512)
    const float* w_proj = (const float*)d_in[2];   // (512,512)
    const float* b_proj = (const float*)d_in[3];   // (512,)
    const float* paramR = (const float*)d_in[4];   // (1,)
    float* out = (float*)d_out;                    // (4,256,512)

    float *qkv, *att;
    cudaGetSymbolAddress((void**)&qkv, g_qkv);
    cudaGetSymbolAddress((void**)&att, g_att);

    cudaFuncSetAttribute(attn_kernel,
                         cudaFuncAttributeMaxDynamicSharedMemorySize, 131072);

    // 1) QKV projection: [1024][1536] = x @ w_qkv^T.  BN=64 -> grid (24,16)=384
    gemm_f2<8, false><<<dim3(1536 / 64, 1024 / 64), 256>>>(
        x, w_qkv, nullptr, qkv, 1024, 1536, 512);

    // 2) Fourier attention: 128 blocks, 128KB smem
    attn_kernel<<<dim3(4, 32), 256, 131072>>>(qkv, paramR, att);

    // 3) Output projection + bias. BN=32 -> grid (16,16)=256 blocks
    gemm_f2<4, true><<<dim3(512 / 32, 1024 / 64), 256>>>(
        att, w_proj, b_proj, out, 1024, 512, 512);
}

// round 9
// speedup vs baseline: 1.3910x; 1.3910x over previous
#include <cuda_runtime.h>

typedef unsigned long long ull;

// ---- packed f32x2 helpers (sm_100+) ---------------------------------------
__device__ __forceinline__ ull f2pack(float lo, float hi) {
    ull r; asm("mov.b64 %0, {%1, %2};" : "=l"(r) : "f"(lo), "f"(hi)); return r;
}
__device__ __forceinline__ void f2unpack(ull v, float& lo, float& hi) {
    asm("mov.b64 {%0, %1}, %2;" : "=f"(lo), "=f"(hi) : "l"(v));
}
__device__ __forceinline__ ull ffma2(ull a, ull b, ull c) {
    ull d; asm("fma.rn.f32x2 %0, %1, %2, %3;" : "=l"(d) : "l"(a), "l"(b), "l"(c));
    return d;
}
__device__ __forceinline__ ull fmul2(ull a, ull b) {
    ull d; asm("mul.rn.f32x2 %0, %1, %2;" : "=l"(d) : "l"(a), "l"(b));
    return d;
}
__device__ __forceinline__ ull fadd2(ull a, ull b) {
    ull d; asm("add.rn.f32x2 %0, %1, %2;" : "=l"(d) : "l"(a), "l"(b));
    return d;
}

// Scratch (device globals — no allocation allowed)
__device__ float g_qp[2 * 1024 * 1536];   // qkv partials (2 K-split slabs)
__device__ float g_att[1024 * 512];       // attention output
__device__ float g_op[4 * 1024 * 512];    // proj partials (4 K-split slabs)

// ---------------------------------------------------------------------------
// GEMM (R2-proven structure + K-split): C_z[M][N] = A[:, Kz] @ B[:, Kz]^T.
// blockIdx.z selects the K-slice and output slab. Bias only on slab 0.
// BM=BN=64, BK=16, 256 threads, 4x4 per thread.
// ---------------------------------------------------------------------------
template<int NS, bool HAS_BIAS>
__global__ __launch_bounds__(256) void gemm_kt(
    const float* __restrict__ A, const float* __restrict__ B,
    const float* __restrict__ bias, float* __restrict__ Cparts,
    int M, int N, int K)
{
    const int BM = 64, BN = 64, BK = 16;
    __shared__ float As[BK][BM + 1];
    __shared__ float Bs[BK][BN + 4];

    int tid = threadIdx.x;
    int tx = tid & 15;
    int ty = tid >> 4;
    int row0 = blockIdx.y * BM;
    int col0 = blockIdx.x * BN;
    int z = blockIdx.z;
    int kStart = z * (K / NS);
    int kEnd = kStart + K / NS;
    float* C = Cparts + (size_t)z * M * N;

    float acc[4][4] = {};

    int lm = tid >> 2;
    int lk = (tid & 3) * 4;
    const float* Ap = A + (size_t)(row0 + lm) * K + lk;
    const float* Bp = B + (size_t)(col0 + lm) * K + lk;

    for (int k0 = kStart; k0 < kEnd; k0 += BK) {
        float4 a4 = *(const float4*)(Ap + k0);
        float4 b4 = *(const float4*)(Bp + k0);
        As[lk + 0][lm] = a4.x; As[lk + 1][lm] = a4.y;
        As[lk + 2][lm] = a4.z; As[lk + 3][lm] = a4.w;
        Bs[lk + 0][lm] = b4.x; Bs[lk + 1][lm] = b4.y;
        Bs[lk + 2][lm] = b4.z; Bs[lk + 3][lm] = b4.w;
        __syncthreads();

        #pragma unroll
        for (int k = 0; k < BK; k++) {
            float af[4];
            #pragma unroll
            for (int i = 0; i < 4; i++) af[i] = As[k][ty * 4 + i];
            float4 bb = *(const float4*)&Bs[k][tx * 4];
            float bf[4] = {bb.x, bb.y, bb.z, bb.w};
            #pragma unroll
            for (int i = 0; i < 4; i++)
                #pragma unroll
                for (int j = 0; j < 4; j++)
                    acc[i][j] = fmaf(af[i], bf[j], acc[i][j]);
        }
        __syncthreads();
    }

    int c = col0 + tx * 4;
    float4 bv = make_float4(0.f, 0.f, 0.f, 0.f);
    if (HAS_BIAS && z == 0) bv = *(const float4*)&bias[c];
    #pragma unroll
    for (int i = 0; i < 4; i++) {
        int r = row0 + ty * 4 + i;
        float4 o;
        o.x = acc[i][0] + bv.x;
        o.y = acc[i][1] + bv.y;
        o.z = acc[i][2] + bv.z;
        o.w = acc[i][3] + bv.w;
        *(float4*)&C[(size_t)r * N + c] = o;
    }
}

// Sum 4 partial slabs into out (proj epilogue). n4 = element count / 4.
__global__ __launch_bounds__(256) void add4(
    const float* __restrict__ P, float* __restrict__ out, int n4)
{
    int i = blockIdx.x * 256 + threadIdx.x;
    if (i < n4) {
        const float4* p = (const float4*)P;
        float4 a = p[i], b = p[i + n4], c = p[i + 2 * n4], d = p[i + 3 * n4];
        float4 o;
        o.x = (a.x + b.x) + (c.x + d.x);
        o.y = (a.y + b.y) + (c.y + d.y);
        o.z = (a.z + b.z) + (c.z + d.z);
        o.w = (a.w + b.w) + (c.w + d.w);
        ((float4*)out)[i] = o;
    }
}

// ---------------------------------------------------------------------------
// Fourier attention, MUFU-free inner loop via angle-subtraction identity:
//   sin(R(q-k)) = sin(Rq)cos(Rk) - cos(Rq)sin(Rk)
// Per token we precompute sin/cos once; the O(N^2*Dh) core is pure packed
// f32x2 fixed-pipe math. 64-dim product split across lane pairs (32 dims
// each), combined with shfl.bfly(16).
//
// Grid (4 q-tiles, B*H=32), 256 threads:
//   warp w: qgroup = w&3 (16 queries), sub = w>>2 (key half of stage)
//   lane:   q = qgroup*16 + (lane&15), half = lane>>4 (dim half)
// Keys staged 128 at a time in smem: kU=-R*k, sin(Rk), cos(Rk), V (128KB).
// qkv input arrives as 2 K-split slabs; loader sums them.
// ---------------------------------------------------------------------------
__global__ __launch_bounds__(256) void attn_kernel(
    const float* __restrict__ qkv0, const float* __restrict__ qkv1,
    const float* __restrict__ paramR, float* __restrict__ outp)
{
    extern __shared__ float sm[];
    float* kU  = sm;            // [128][64]  -R*k
    float* kSn = sm + 8192;     // [128][64]  sin(R*k)
    float* kCs = sm + 16384;    // [128][64]  cos(R*k)
    float* kV  = sm + 24576;    // [128][64]  v

    int tid = threadIdx.x;
    int warp = tid >> 5, lane = tid & 31;
    int qg = warp & 3, sub = warp >> 2;
    int q = qg * 16 + (lane & 15);
    int half = lane >> 4;
    int bh = blockIdx.y;
    int b = bh >> 3, h = bh & 7;
    int qbase = blockIdx.x * 64;
    float R = paramR[0];

    const float* base0 = qkv0 + (size_t)(b * 256) * 1536 + h * 64;
    const float* base1 = qkv1 + (size_t)(b * 256) * 1536 + h * 64;

    // ---- q-side precompute: this thread's 32 dims --------------------------
    ull qu[16], qs[16], qnc[16];
    {
        const float* qp0 = base0 + (size_t)(qbase + q) * 1536 + half * 32;
        const float* qp1 = base1 + (size_t)(qbase + q) * 1536 + half * 32;
        #pragma unroll
        for (int j = 0; j < 16; j++) {
            float x0 = R * (qp0[2 * j]     + qp1[2 * j]);
            float x1 = R * (qp0[2 * j + 1] + qp1[2 * j + 1]);
            float s0, c0, s1, c1;
            __sincosf(x0, &s0, &c0);
            __sincosf(x1, &s1, &c1);
            qu[j]  = f2pack(x0, x1);
            qs[j]  = f2pack(s0, s1);
            qnc[j] = f2pack(-c0, -c1);
        }
    }
    float R64;
    { float p = R; p *= p; p *= p; p *= p; p *= p; p *= p; p *= p; R64 = p; }
    const ull ONE2 = f2pack(1.f, 1.f);

    ull acc[16];
    #pragma unroll
    for (int j = 0; j < 16; j++) acc[j] = 0ull;
    float sumA = 0.f;

    for (int stage = 0; stage < 2; stage++) {
        __syncthreads();
        // ---- stage 128 keys: compute -R*k, sin, cos; copy V ----------------
        for (int i = tid; i < 2048; i += 256) {
            int r = i >> 4, d4 = (i & 15) << 2;
            size_t off = (size_t)(stage * 128 + r) * 1536 + d4;
            float4 ka = *(const float4*)(base0 + off + 512);
            float4 kb = *(const float4*)(base1 + off + 512);
            float4 va = *(const float4*)(base0 + off + 1024);
            float4 vb = *(const float4*)(base1 + off + 1024);
            float xs[4] = {ka.x + kb.x, ka.y + kb.y, ka.z + kb.z, ka.w + kb.w};
            float us[4], ss[4], cs[4];
            #pragma unroll
            for (int e = 0; e < 4; e++) {
                float xx = R * xs[e];
                us[e] = -xx;
                __sincosf(xx, &ss[e], &cs[e]);
            }
            int o = r * 64 + d4;
            *(float4*)&kU[o]  = make_float4(us[0], us[1], us[2], us[3]);
            *(float4*)&kSn[o] = make_float4(ss[0], ss[1], ss[2], ss[3]);
            *(float4*)&kCs[o] = make_float4(cs[0], cs[1], cs[2], cs[3]);
            *(float4*)&kV[o]  = make_float4(va.x + vb.x, va.y + vb.y,
                                            va.z + vb.z, va.w + vb.w);
        }
        __syncthreads();

        // ---- 64 keys for this sub ------------------------------------------
        for (int kk = 0; kk < 64; kk++) {
            int r = sub * 64 + kk;
            const ulonglong2* pU = (const ulonglong2*)&kU [r * 64 + half * 32];
            const ulonglong2* pS = (const ulonglong2*)&kSn[r * 64 + half * 32];
            const ulonglong2* pC = (const ulonglong2*)&kCs[r * 64 + half * 32];
            const ulonglong2* pV = (const ulonglong2*)&kV [r * 64 + half * 32];

            float part = 1.f;
            #pragma unroll
            for (int c = 0; c < 2; c++) {
                ull pnA = ONE2, pnB = ONE2, pdA = ONE2, pdB = ONE2;
                #pragma unroll
                for (int t = 0; t < 4; t++) {
                    int j = c * 8 + t * 2;
                    ulonglong2 U  = pU[c * 4 + t];
                    ulonglong2 S  = pS[c * 4 + t];
                    ulonglong2 Cc = pC[c * 4 + t];
                    ull u2 = fadd2(qu[j], U.x);
                    ull s2 = ffma2(qs[j], Cc.x, fmul2(qnc[j], S.x));
                    pnA = fmul2(pnA, s2);  pdA = fmul2(pdA, u2);
                    ull u3 = fadd2(qu[j + 1], U.y);
                    ull s3 = ffma2(qs[j + 1], Cc.y, fmul2(qnc[j + 1], S.y));
                    pnB = fmul2(pnB, s3);  pdB = fmul2(pdB, u3);
                }
                ull pn2 = fmul2(pnA, pnB);
                ull pd2 = fmul2(pdA, pdB);
                float pnl, pnh, pdl, pdh;
                f2unpack(pn2, pnl, pnh);
                f2unpack(pd2, pdl, pdh);
                float pn = pnl * pnh, pd = pdl * pdh;
                if (pd != 0.f) {
                    part *= __fdividef(pn, pd);
                } else {
                    // exact-zero diff on some dim (reference near0 -> factor R,
                    // i.e. ratio contribution 1). Essentially never taken.
                    #pragma unroll 1
                    for (int t = 0; t < 8; t++) {
                        int j = c * 8 + t;
                        ull U1 = ((const ull*)pU)[j];
                        ull u2 = fadd2(qu[j], U1);
                        float a, bb;
                        f2unpack(u2, a, bb);
                        if (a  != 0.f) part *= __fdividef(__sinf(a), a);
                        if (bb != 0.f) part *= __fdividef(__sinf(bb), bb);
                    }
                }
            }
            float other = __shfl_xor_sync(0xffffffffu, part, 16);
            float sc = R64 * part * other;
            float a2 = sc * sc;
            float a4 = a2 * a2;
            sumA += a4;
            ull a42 = f2pack(a4, a4);
            #pragma unroll
            for (int t = 0; t < 8; t++) {
                ulonglong2 V = pV[t];
                acc[2 * t]     = ffma2(a42, V.x, acc[2 * t]);
                acc[2 * t + 1] = ffma2(a42, V.y, acc[2 * t + 1]);
            }
        }
    }
    __syncthreads();   // all reads of k-arrays done — reuse smem

    // ---- combine partials: accR[sub][q][64], sumR[sub][q] ------------------
    float* accR = sm;            // 2*64*64 = 8192 floats
    float* sumR = sm + 8192;     // 128 floats
    {
        float* ap = &accR[(sub * 64 + q) * 64 + half * 32];
        #pragma unroll
        for (int j = 0; j < 16; j++) {
            float lo, hi;
            f2unpack(acc[j], lo, hi);
            ap[2 * j] = lo; ap[2 * j + 1] = hi;
        }
        if (half == 0) sumR[sub * 64 + q] = sumA;
    }
    __syncthreads();

    {
        int q2 = tid >> 2;
        int d0 = (tid & 3) * 16;
        float inv = __fdividef(1.f, sumR[q2] + sumR[64 + q2] + 1e-6f);
        float* dst = outp + (size_t)(b * 256 + qbase + q2) * 512 + h * 64;
        const float* a0 = &accR[q2 * 64];
        const float* a1 = &accR[(64 + q2) * 64];
        #pragma unroll
        for (int d = d0; d < d0 + 16; d++)
            dst[d] = (a0[d] + a1[d]) * inv;
    }
}

// ---------------------------------------------------------------------------
extern "C" void kernel_launch(void* const* d_in, const int* in_sizes, int n_in,
                              void* d_out, int out_size)
{
    const float* x      = (const float*)d_in[0];   // (4,256,512)
    const float* w_qkv  = (const float*)d_in[1];   // (1536,512)
    const float* w_proj = (const float*)d_in[2];   // (512,512)
    const float* b_proj = (const float*)d_in[3];   // (512,)
    const float* paramR = (const float*)d_in[4];   // (1,)
    float* out = (float*)d_out;                    // (4,256,512)

    float *qp, *att, *op;
    cudaGetSymbolAddress((void**)&qp,  g_qp);
    cudaGetSymbolAddress((void**)&att, g_att);
    cudaGetSymbolAddress((void**)&op,  g_op);

    cudaFuncSetAttribute(attn_kernel,
                         cudaFuncAttributeMaxDynamicSharedMemorySize, 131072);

    // 1) QKV projection, K-split 2: grid (24,16,2) = 768 blocks
    gemm_kt<2, false><<<dim3(1536 / 64, 1024 / 64, 2), 256>>>(
        x, w_qkv, nullptr, qp, 1024, 1536, 512);

    // 2) Fourier attention (sums the two qkv slabs in its loader)
    attn_kernel<<<dim3(4, 32), 256, 131072>>>(
        qp, qp + (size_t)1024 * 1536, paramR, att);

    // 3) Output projection, K-split 4: grid (8,16,4) = 512 blocks
    gemm_kt<4, true><<<dim3(512 / 64, 1024 / 64, 4), 256>>>(
        att, w_proj, b_proj, op, 1024, 512, 512);

    // 4) Sum proj slabs into final output
    add4<<<dim3((1024 * 512 / 4 + 255) / 256), 256>>>(op, out, 1024 * 512 / 4);
}